// round 1
// baseline (speedup 1.0000x reference)
#include <cuda_runtime.h>

#define KBINS 8
#define BVAL 3.0f
#define DIMN 32
#define HID 32
#define LNUM 31
#define NP 23          // 3K-1
#define MIN_BW 1e-3f
#define MIN_D 1e-3f
#define BATCH 65536
// log(exp(1 - MIN_D) - 1): edge-derivative pad constant
#define CPAD 0.5397416f

__device__ __forceinline__ float fast_tanh(float x) {
    // tanh(x) = 1 - 2/(exp(2x)+1); exact enough (rel err ~1e-6), overflow-safe
    float e = __expf(2.0f * x);
    return 1.0f - __fdividef(2.0f, e + 1.0f);
}

__device__ __forceinline__ float softplusf(float x) {
    // stable: max(x,0) + log1p(exp(-|x|))
    return fmaxf(x, 0.0f) + __logf(1.0f + __expf(-fabsf(x)));
}

// softmax over 8 values p[off..off+7], result scaled: out[i] = scale * e_i / sum
__device__ __forceinline__ void softmax8(const float* p, float scale, float* out) {
    float m = p[0];
#pragma unroll
    for (int i = 1; i < KBINS; i++) m = fmaxf(m, p[i]);
    float s = 0.0f;
#pragma unroll
    for (int i = 0; i < KBINS; i++) { out[i] = __expf(p[i] - m); s += out[i]; }
    float inv = __fdividef(scale, s);
#pragma unroll
    for (int i = 0; i < KBINS; i++) out[i] *= inv;
}

// Rational-quadratic spline forward for one scalar. p = 23 raw conditioner params.
__device__ __forceinline__ float spline_fwd(float xin, const float* p, float* ldo) {
    // ---- widths ----
    float wu[KBINS], w_[KBINS];
    softmax8(p, 2.0f * BVAL, wu);          // Wu = 2B * softmax(p[:8])
    softmax8(wu, 1.0f - MIN_BW * KBINS, w_); // inner softmax, scaled
#pragma unroll
    for (int i = 0; i < KBINS; i++) w_[i] += MIN_BW;
    // ---- heights ----
    float hu[KBINS], h_[KBINS];
    softmax8(p + KBINS, 2.0f * BVAL, hu);
    softmax8(hu, 1.0f - MIN_BW * KBINS, h_);
#pragma unroll
    for (int i = 0; i < KBINS; i++) h_[i] += MIN_BW;

    // cumulative knots (edges pinned)
    float cw[KBINS + 1], ch[KBINS + 1];
    cw[0] = -BVAL; ch[0] = -BVAL;
    {
        float c = 0.0f;
#pragma unroll
        for (int k = 0; k < KBINS; k++) { c += w_[k]; cw[k + 1] = 2.0f * BVAL * c - BVAL; }
        cw[KBINS] = BVAL;
        c = 0.0f;
#pragma unroll
        for (int k = 0; k < KBINS; k++) { c += h_[k]; ch[k + 1] = 2.0f * BVAL * c - BVAL; }
        ch[KBINS] = BVAL;
    }

    // knot derivatives: edges pinned to 1, interior = MIN_D + softplus(softplus(p))
    float dv[KBINS + 1];
    {
        float de = MIN_D + softplusf(CPAD);
        dv[0] = de; dv[KBINS] = de;
#pragma unroll
        for (int j = 0; j < KBINS - 1; j++)
            dv[j + 1] = MIN_D + softplusf(softplusf(p[2 * KBINS + j]));
    }

    bool inside = (xin >= -BVAL) && (xin <= BVAL);
    float xc = fminf(fmaxf(xin, -BVAL), BVAL);

    // bin select (predicated, fully unrolled -> no local memory)
    float in_cw = cw[0], in_ch = ch[0];
    float in_w = cw[1] - cw[0], in_h = ch[1] - ch[0];
    float d0 = dv[0], d1 = dv[1];
#pragma unroll
    for (int k = 1; k < KBINS; k++) {
        if (xc >= cw[k]) {
            in_cw = cw[k]; in_ch = ch[k];
            in_w = cw[k + 1] - cw[k]; in_h = ch[k + 1] - ch[k];
            d0 = dv[k]; d1 = dv[k + 1];
        }
    }

    float invw = __fdividef(1.0f, in_w);
    float delta = in_h * invw;
    float th = (xc - in_cw) * invw;
    float tt = th * (1.0f - th);
    float num = in_h * (delta * th * th + d0 * tt);
    float den = delta + (d0 + d1 - 2.0f * delta) * tt;
    float outv = in_ch + __fdividef(num, den);
    float omt = 1.0f - th;
    float dnum = delta * delta * (d1 * th * th + 2.0f * delta * tt + d0 * omt * omt);
    float ld = __logf(dnum) - 2.0f * __logf(den);

    *ldo = inside ? ld : 0.0f;
    return inside ? outv : xin;
}

__global__ __launch_bounds__(128) void nsf_ar_kernel(
    const float* __restrict__ x, const float* __restrict__ init_param,
    const float* __restrict__ w1, const float* __restrict__ b1,
    const float* __restrict__ w2, const float* __restrict__ b2,
    const float* __restrict__ w3, const float* __restrict__ b3,
    float* __restrict__ zout, float* __restrict__ ldout, int write_ld)
{
    __shared__ float xs[128][33];     // padded: conflict-free per-thread row reads
    __shared__ float w1s[31][32];
    __shared__ float w2s[32][32];
    __shared__ float w3s[32][24];     // col-padded (23->24)
    __shared__ float b1s[32], b2s[32], b3s[NP];

    const int t = threadIdx.x;
    const int b0 = blockIdx.x * 128;

    // stage x tile (coalesced)
    for (int i = t; i < 128 * 32; i += 128) xs[i >> 5][i & 31] = x[b0 * 32 + i];
    __syncthreads();

    const int b = b0 + t;
    float ldacc;
    {
        float p[NP];
#pragma unroll
        for (int j = 0; j < NP; j++) p[j] = init_param[j];   // warp-uniform broadcast
        float ld;
        float z0 = spline_fwd(xs[t][0], p, &ld);
        zout[b * DIMN] = z0;
        ldacc = ld;
    }

    for (int l = 0; l < LNUM; l++) {
        __syncthreads();
        // stage layer-l weights
        float* w1f = &w1s[0][0];
        float* w2f = &w2s[0][0];
        for (int i = t; i < 31 * 32; i += 128) w1f[i] = w1[l * 992 + i];
        for (int i = t; i < 32 * 32; i += 128) w2f[i] = w2[l * 1024 + i];
        for (int i = t; i < 32 * 23; i += 128) w3s[i / 23][i % 23] = w3[l * 736 + i];
        if (t < 32) { b1s[t] = b1[l * 32 + t]; b2s[t] = b2[l * 32 + t]; }
        if (t < NP) b3s[t] = b3[l * NP + t];
        __syncthreads();

        // h1 = tanh(x[:, :l+1] @ w1[l, :l+1, :] + b1)   (causal mask -> d <= l only)
        float h1[HID];
#pragma unroll
        for (int h = 0; h < HID; h++) h1[h] = b1s[h];
        for (int d = 0; d <= l; d++) {
            float xd = xs[t][d];
#pragma unroll
            for (int h = 0; h < HID; h++) h1[h] = fmaf(xd, w1s[d][h], h1[h]);
        }
#pragma unroll
        for (int h = 0; h < HID; h++) h1[h] = fast_tanh(h1[h]);

        // h2 = tanh(h1 @ w2[l] + b2)
        float h2[HID];
#pragma unroll
        for (int h = 0; h < HID; h++) h2[h] = b2s[h];
#pragma unroll
        for (int d = 0; d < HID; d++) {
            float v = h1[d];
#pragma unroll
            for (int h = 0; h < HID; h++) h2[h] = fmaf(v, w2s[d][h], h2[h]);
        }
#pragma unroll
        for (int h = 0; h < HID; h++) h2[h] = fast_tanh(h2[h]);

        // p = h2 @ w3[l] + b3
        float p[NP];
#pragma unroll
        for (int j = 0; j < NP; j++) p[j] = b3s[j];
#pragma unroll
        for (int d = 0; d < HID; d++) {
            float v = h2[d];
#pragma unroll
            for (int j = 0; j < NP; j++) p[j] = fmaf(v, w3s[d][j], p[j]);
        }

        // spline for dim l+1
        float ld;
        float zz = spline_fwd(xs[t][l + 1], p, &ld);
        zout[b * DIMN + l + 1] = zz;
        ldacc += ld;
    }

    if (write_ld) ldout[b] = ldacc;
}

extern "C" void kernel_launch(void* const* d_in, const int* in_sizes, int n_in,
                              void* d_out, int out_size) {
    const float* x          = (const float*)d_in[0];
    const float* init_param = (const float*)d_in[1];
    const float* w1 = (const float*)d_in[2];
    const float* b1 = (const float*)d_in[3];
    const float* w2 = (const float*)d_in[4];
    const float* b2 = (const float*)d_in[5];
    const float* w3 = (const float*)d_in[6];
    const float* b3 = (const float*)d_in[7];

    float* out = (float*)d_out;
    int write_ld = (out_size >= BATCH * DIMN + BATCH) ? 1 : 0;

    nsf_ar_kernel<<<BATCH / 128, 128>>>(x, init_param, w1, b1, w2, b2, w3, b3,
                                        out, out + (size_t)BATCH * DIMN, write_ld);
}